// round 14
// baseline (speedup 1.0000x reference)
#include <cuda_runtime.h>
#include <cuda_fp16.h>
#include <cstdint>

// out = elu(input @ W)  [reference's softmax(eye-mask) == Identity exactly]
// fp32 GEMM M=8192 N=2048 K=2048, single fp16 term on mma.sync.m16n8k16
// (measured rel_err 3.0e-4 < 1e-3).
// R13: tail attack. R5/R12 both measure 398 TF/s WITH a 3.46-wave tail ->
//   ~460 TF/s tail-free HMMA ceiling (needs occ-2; R8 occ-1 = 319).
//   CTA 128x64, 8 warps (warp 32x32), occ-2 => grid 2048 = 6.92 waves
//   (98.8% wave eff vs 86.5%). 4-stage ring of 24KB stages (192KB/SM).
//   Crossbar check: 352 B/MMA * 0.19 MMA/cyc = 67 B/cyc << 128 ok.

#define GM 8192
#define GN 2048
#define GK 2048

#define BM 128
#define BN 64
#define BK 64
#define NTHREADS 256
#define NCHUNK (GK / BK)   // 32

// ---------------- scratch (fp16 operands) ----------------
__device__ __half g_Ah[(size_t)GM * GK];
__device__ __half g_Bh[(size_t)GN * GK];   // W^T, K-major rows

// ---------------- smem stage layout ----------------
// per stage: Ah 16K | Bh 8K   (rows of 128B, SW128)
#define SA 0
#define SB 16384
#define STAGE_BYTES 24576
#define NSTAGE 4
#define SMEM_TOTAL (NSTAGE * STAGE_BYTES)   // 98304/CTA; x2 CTAs = 192KB/SM

__device__ __forceinline__ uint32_t smem_u32(const void* p) {
    uint32_t a;
    asm("{ .reg .u64 t; cvta.to.shared.u64 t, %1; cvt.u32.u64 %0, t; }" : "=r"(a) : "l"(p));
    return a;
}
__device__ __forceinline__ void cp16(uint32_t dst, const void* src) {
    asm volatile("cp.async.cg.shared.global [%0], [%1], 16;" :: "r"(dst), "l"(src));
}
__device__ __forceinline__ void cp_commit() {
    asm volatile("cp.async.commit_group;" ::: "memory");
}
__device__ __forceinline__ void cp_wait2() {
    asm volatile("cp.async.wait_group 2;" ::: "memory");
}
__device__ __forceinline__ void ldsm4(uint32_t addr, uint32_t& r0, uint32_t& r1,
                                      uint32_t& r2, uint32_t& r3) {
    asm volatile("ldmatrix.sync.aligned.m8n8.x4.shared.b16 {%0,%1,%2,%3}, [%4];"
                 : "=r"(r0), "=r"(r1), "=r"(r2), "=r"(r3) : "r"(addr));
}
__device__ __forceinline__ void mma16816(float& d0, float& d1, float& d2, float& d3,
                                         uint32_t a0, uint32_t a1, uint32_t a2, uint32_t a3,
                                         uint32_t b0, uint32_t b1) {
    asm volatile(
        "mma.sync.aligned.m16n8k16.row.col.f32.f16.f16.f32 "
        "{%0,%1,%2,%3}, {%4,%5,%6,%7}, {%8,%9}, {%0,%1,%2,%3};"
        : "+f"(d0), "+f"(d1), "+f"(d2), "+f"(d3)
        : "r"(a0), "r"(a1), "r"(a2), "r"(a3), "r"(b0), "r"(b1));
}
__device__ __forceinline__ float elu_f(float x) { return x > 0.0f ? x : expm1f(x); }

// ---------------- merged conversion kernel ----------------
#define CONV_A_BLOCKS 4096
__global__ __launch_bounds__(256) void conv_kernel(const float* __restrict__ A,
                                                   const float* __restrict__ B) {
    __shared__ float tile[32][33];
    int bid = blockIdx.x;
    int tid = threadIdx.x;
    if (bid < CONV_A_BLOCKS) {
        const float4* A4 = reinterpret_cast<const float4*>(A);
        size_t base = (size_t)bid * 1024 + tid;
        #pragma unroll
        for (int i = 0; i < 4; i++) {
            size_t idx = base + (size_t)i * 256;
            float4 v = A4[idx];
            __half2* ph = reinterpret_cast<__half2*>(g_Ah + idx * 4);
            ph[0] = __half2(__float2half(v.x), __float2half(v.y));
            ph[1] = __half2(__float2half(v.z), __float2half(v.w));
        }
    } else {
        int b = bid - CONV_A_BLOCKS;          // 0..4095
        int n0 = (b & 63) * 32;
        int k0 = (b >> 6) * 32;
        int tx = tid & 31, ty = tid >> 5;
        #pragma unroll
        for (int j = 0; j < 32; j += 8)
            tile[ty + j][tx] = B[(size_t)(k0 + ty + j) * GN + n0 + tx];
        __syncthreads();
        #pragma unroll
        for (int j = 0; j < 32; j += 8) {
            float x = tile[tx][ty + j];
            g_Bh[(size_t)(n0 + ty + j) * GK + k0 + tx] = __float2half(x);
        }
    }
}

// ---------------- hoisted stage fill (one BK=64 chunk) ----------------
// s0: per-thread swizzled smem offset (valid for both A and B tiles: with 256
// threads, row index steps by 32 (==0 mod 8) so the SW128 mask is invariant).
__device__ __forceinline__ void fill_stage2(uint32_t sbase, uint32_t s0,
                                            const char* pA, const char* pB,
                                            int kc) {
    const size_t koff = (size_t)kc * 128;
    #pragma unroll
    for (int j = 0; j < 4; j++)
        cp16(sbase + SA + s0 + j * 4096, pA + koff + (size_t)j * 131072);
    #pragma unroll
    for (int j = 0; j < 2; j++)
        cp16(sbase + SB + s0 + j * 4096, pB + koff + (size_t)j * 131072);
}

// ---------------- main GEMM kernel ----------------
__global__ __launch_bounds__(NTHREADS, 2)
void gat_mma_kernel(float* __restrict__ C) {
    extern __shared__ char smem[];
    uint32_t sb = smem_u32(smem);
    const int tid  = threadIdx.x;
    const int wid  = tid >> 5;
    const int lane = tid & 31;
    const int m0 = blockIdx.y * BM;
    const int n0 = blockIdx.x * BN;
    const int warp_m = wid & 3;    // 4 M-tiles of 32
    const int warp_n = wid >> 2;   // 2 N-tiles of 32

    // per-thread fill addressing (hoisted)
    const uint32_t s0 = (uint32_t)((tid >> 3) * 128 +
                        (((tid & 7) * 16) ^ (((tid >> 3) & 7) << 4)));
    const char* pA = (const char*)g_Ah + (size_t)(m0 + (tid >> 3)) * 4096 + (tid & 7) * 16;
    const char* pB = (const char*)g_Bh + (size_t)(n0 + (tid >> 3)) * 4096 + (tid & 7) * 16;

    float acc[2][4][4];
    #pragma unroll
    for (int i = 0; i < 2; i++)
        #pragma unroll
        for (int j = 0; j < 4; j++)
            #pragma unroll
            for (int t = 0; t < 4; t++) acc[i][j][t] = 0.0f;

    // per-lane swizzled ldsm bases:
    // SWZ(row*128 + c) == row*128 + (c ^ ((row&7)<<4))  for c < 128
    const int a_row_l = lane & 15;
    const uint32_t a_kb = (uint32_t)((lane >> 4) << 4);
    const int b_j = lane >> 3;
    const int b_row_l = (lane & 7) + ((b_j >> 1) << 3);
    const uint32_t b_kb = (uint32_t)((b_j & 1) << 4);

    uint32_t baseA[2], xA[2];
    #pragma unroll
    for (int mt = 0; mt < 2; mt++) {
        int row = warp_m * 32 + mt * 16 + a_row_l;
        baseA[mt] = (uint32_t)(row << 7);
        xA[mt]    = (uint32_t)((row & 7) << 4);
    }
    uint32_t baseB[2], xB[2];
    #pragma unroll
    for (int np = 0; np < 2; np++) {
        int row = warp_n * 32 + np * 16 + b_row_l;
        baseB[np] = (uint32_t)(row << 7);
        xB[np]    = (uint32_t)((row & 7) << 4);
    }

    // prologue: fill 4 stages (chunks 0..3)
    #pragma unroll
    for (int s = 0; s < NSTAGE; s++) {
        fill_stage2(sb + (uint32_t)s * STAGE_BYTES, s0, pA, pB, s);
        cp_commit();
    }

    uint32_t stage = sb;                           // slot of chunk k
    uint32_t prev  = sb + (NSTAGE - 1) * STAGE_BYTES;  // slot of chunk k-1 (dummy at k=0)
    const uint32_t ring_end = sb + NSTAGE * STAGE_BYTES;

    for (int k = 0; k < NCHUNK; k++) {
        cp_wait2();        // chunk k resident (<=2 newer groups in flight)
        __syncthreads();   // all warps done reading chunk k-1; writes visible

        // refill chunk k-1's slot with chunk k+3
        if (k >= 1) {
            int kc = k + 3;
            if (kc < NCHUNK) fill_stage2(prev, s0, pA, pB, kc);
            cp_commit();   // empty group when kc >= NCHUNK keeps accounting
        }

        #pragma unroll
        for (int ks = 0; ks < 4; ks++) {
            const uint32_t kb = (uint32_t)(ks * 32);

            // B fragments: 2 ldsm.x4 cover 4 n-tiles (warp's 32 cols)
            uint32_t bh[4][2];
            #pragma unroll
            for (int np = 0; np < 2; np++) {
                uint32_t ad = stage + SB + baseB[np] + ((kb + b_kb) ^ xB[np]);
                uint32_t r0, r1, r2, r3;
                ldsm4(ad, r0, r1, r2, r3);
                bh[np * 2 + 0][0] = r0; bh[np * 2 + 0][1] = r1;
                bh[np * 2 + 1][0] = r2; bh[np * 2 + 1][1] = r3;
            }
            // A fragments: 2 ldsm.x4 (warp's 32 rows)
            uint32_t ah[2][4];
            #pragma unroll
            for (int mt = 0; mt < 2; mt++) {
                uint32_t ad = stage + SA + baseA[mt] + ((kb + a_kb) ^ xA[mt]);
                ldsm4(ad, ah[mt][0], ah[mt][1], ah[mt][2], ah[mt][3]);
            }
            #pragma unroll
            for (int mt = 0; mt < 2; mt++)
                #pragma unroll
                for (int nt = 0; nt < 4; nt++)
                    mma16816(acc[mt][nt][0], acc[mt][nt][1], acc[mt][nt][2], acc[mt][nt][3],
                             ah[mt][0], ah[mt][1], ah[mt][2], ah[mt][3],
                             bh[nt][0], bh[nt][1]);
        }

        prev = stage;
        stage += STAGE_BYTES;
        if (stage == ring_end) stage = sb;
    }

    // ---------------- epilogue: fused elu, float2 stores ----------------
    const int gp  = lane >> 2;
    const int tg2 = (lane & 3) * 2;
    #pragma unroll
    for (int mt = 0; mt < 2; mt++) {
        int mrow = m0 + warp_m * 32 + mt * 16 + gp;
        #pragma unroll
        for (int nt = 0; nt < 4; nt++) {
            int ncol = n0 + warp_n * 32 + nt * 8 + tg2;
            float2 v0, v1;
            v0.x = elu_f(acc[mt][nt][0]);
            v0.y = elu_f(acc[mt][nt][1]);
            v1.x = elu_f(acc[mt][nt][2]);
            v1.y = elu_f(acc[mt][nt][3]);
            *reinterpret_cast<float2*>(C + (size_t)mrow * GN + ncol) = v0;
            *reinterpret_cast<float2*>(C + (size_t)(mrow + 8) * GN + ncol) = v1;
        }
    }
}

// ---------------- launch ----------------
extern "C" void kernel_launch(void* const* d_in, const int* in_sizes, int n_in,
                              void* d_out, int out_size) {
    const float* input = (const float*)d_in[0];   // [8192, 2048]
    const float* W     = (const float*)d_in[2];   // [2048, 2048]
    float*       out   = (float*)d_out;

    cudaFuncSetAttribute(gat_mma_kernel,
                         cudaFuncAttributeMaxDynamicSharedMemorySize, SMEM_TOTAL);

    conv_kernel<<<CONV_A_BLOCKS + 4096, 256>>>(input, W);
    gat_mma_kernel<<<dim3(GN / BN, GM / BM), NTHREADS, SMEM_TOTAL>>>(out);
}

// round 15
// speedup vs baseline: 1.2023x; 1.2023x over previous
#include <cuda_runtime.h>
#include <cuda_fp16.h>
#include <cstdint>

// out = elu(input @ W)  [reference's softmax(eye-mask) == Identity exactly]
// fp32 GEMM M=8192 N=2048 K=2048, single fp16 term on mma.sync.m16n8k16
// (measured rel_err 3.0e-4 < 1e-3).
// R14: R12 platform (occ-2, CTA 128x128, 8 warps, warp 64x32, 3-stage,
//   1 sync/chunk, hoisted fill addressing — best at 193us). Changes:
//   - k-loop unrolled by NSTAGE=3: compile-time stage offsets, no rotating
//     pointers, no k>=1 branch.
//   - conv: A stores float4 (8 halfs), W stores half2 (2x store efficiency).

#define GM 8192
#define GN 2048
#define GK 2048

#define BM 128
#define BN 128
#define BK 64
#define NTHREADS 256
#define NCHUNK (GK / BK)   // 32

// ---------------- scratch (fp16 operands) ----------------
__device__ __half g_Ah[(size_t)GM * GK];
__device__ __half g_Bh[(size_t)GN * GK];   // W^T, K-major rows

// ---------------- smem stage layout ----------------
#define SA 0
#define SB 16384
#define STAGE_BYTES 32768
#define NSTAGE 3
#define SMEM_TOTAL (NSTAGE * STAGE_BYTES)   // 98304/CTA; x2 CTAs = 192KB/SM

__device__ __forceinline__ uint32_t smem_u32(const void* p) {
    uint32_t a;
    asm("{ .reg .u64 t; cvta.to.shared.u64 t, %1; cvt.u32.u64 %0, t; }" : "=r"(a) : "l"(p));
    return a;
}
__device__ __forceinline__ void cp16(uint32_t dst, const void* src) {
    asm volatile("cp.async.cg.shared.global [%0], [%1], 16;" :: "r"(dst), "l"(src));
}
__device__ __forceinline__ void cp_commit() {
    asm volatile("cp.async.commit_group;" ::: "memory");
}
__device__ __forceinline__ void cp_wait1() {
    asm volatile("cp.async.wait_group 1;" ::: "memory");
}
__device__ __forceinline__ void ldsm4(uint32_t addr, uint32_t& r0, uint32_t& r1,
                                      uint32_t& r2, uint32_t& r3) {
    asm volatile("ldmatrix.sync.aligned.m8n8.x4.shared.b16 {%0,%1,%2,%3}, [%4];"
                 : "=r"(r0), "=r"(r1), "=r"(r2), "=r"(r3) : "r"(addr));
}
__device__ __forceinline__ void mma16816(float& d0, float& d1, float& d2, float& d3,
                                         uint32_t a0, uint32_t a1, uint32_t a2, uint32_t a3,
                                         uint32_t b0, uint32_t b1) {
    asm volatile(
        "mma.sync.aligned.m16n8k16.row.col.f32.f16.f16.f32 "
        "{%0,%1,%2,%3}, {%4,%5,%6,%7}, {%8,%9}, {%0,%1,%2,%3};"
        : "+f"(d0), "+f"(d1), "+f"(d2), "+f"(d3)
        : "r"(a0), "r"(a1), "r"(a2), "r"(a3), "r"(b0), "r"(b1));
}
__device__ __forceinline__ float elu_f(float x) { return x > 0.0f ? x : expm1f(x); }

// ---------------- merged conversion kernel ----------------
// blocks [0, 8192): A fp32 -> fp16, 8 floats/thread, float4 stores
// blocks [8192, 12288): W fp32 -> W^T fp16, smem transpose, half2 stores
#define CONV_A_BLOCKS 8192
__global__ __launch_bounds__(256) void conv_kernel(const float* __restrict__ A,
                                                   const float* __restrict__ B) {
    __shared__ float tile[32][33];
    int bid = blockIdx.x;
    int tid = threadIdx.x;
    if (bid < CONV_A_BLOCKS) {
        const float4* A4 = reinterpret_cast<const float4*>(A);
        size_t u = (size_t)bid * 256 + tid;    // output float4 index (8 halfs)
        float4 v0 = A4[u * 2];
        float4 v1 = A4[u * 2 + 1];
        __half2 h0 = __half2(__float2half(v0.x), __float2half(v0.y));
        __half2 h1 = __half2(__float2half(v0.z), __float2half(v0.w));
        __half2 h2 = __half2(__float2half(v1.x), __float2half(v1.y));
        __half2 h3 = __half2(__float2half(v1.z), __float2half(v1.w));
        float4 out;
        out.x = __uint_as_float(*reinterpret_cast<uint32_t*>(&h0));
        out.y = __uint_as_float(*reinterpret_cast<uint32_t*>(&h1));
        out.z = __uint_as_float(*reinterpret_cast<uint32_t*>(&h2));
        out.w = __uint_as_float(*reinterpret_cast<uint32_t*>(&h3));
        reinterpret_cast<float4*>(g_Ah)[u] = out;
    } else {
        int b = bid - CONV_A_BLOCKS;          // 0..4095
        int n0 = (b & 63) * 32;
        int k0 = (b >> 6) * 32;
        int tx = tid & 31, ty = tid >> 5;     // read phase (32,8)
        #pragma unroll
        for (int j = 0; j < 32; j += 8)
            tile[ty + j][tx] = B[(size_t)(k0 + ty + j) * GN + n0 + tx];
        __syncthreads();
        // write phase: kp = k-pair (0..15), nl = n (0..15), +16 in loop
        int kp = tid & 15, nl = tid >> 4;
        #pragma unroll
        for (int j = 0; j < 32; j += 16) {
            int n = nl + j;
            __half2 h = __half2(__float2half(tile[kp * 2][n]),
                                __float2half(tile[kp * 2 + 1][n]));
            *reinterpret_cast<__half2*>(g_Bh + (size_t)(n0 + n) * GK + k0 + kp * 2) = h;
        }
    }
}

// ---------------- hoisted stage fill (one BK=64 chunk) ----------------
__device__ __forceinline__ void fill_stage2(uint32_t sbase, uint32_t s0,
                                            const char* pA, const char* pB,
                                            int kc) {
    const size_t koff = (size_t)kc * 128;
    #pragma unroll
    for (int j = 0; j < 4; j++) {
        cp16(sbase + SA + s0 + j * 4096, pA + koff + (size_t)j * 131072);
        cp16(sbase + SB + s0 + j * 4096, pB + koff + (size_t)j * 131072);
    }
}

// ---------------- main GEMM kernel ----------------
__global__ __launch_bounds__(NTHREADS, 2)
void gat_mma_kernel(float* __restrict__ C) {
    extern __shared__ char smem[];
    uint32_t sb = smem_u32(smem);
    const int tid  = threadIdx.x;
    const int wid  = tid >> 5;
    const int lane = tid & 31;
    const int m0 = blockIdx.y * BM;
    const int n0 = blockIdx.x * BN;
    const int warp_m = wid & 1;    // 2 M-tiles of 64
    const int warp_n = wid >> 1;   // 4 N-tiles of 32

    // per-thread fill addressing (hoisted; SW128 mask invariant across strides)
    const uint32_t s0 = (uint32_t)((tid >> 3) * 128 +
                        (((tid & 7) * 16) ^ (((tid >> 3) & 7) << 4)));
    const char* pA = (const char*)g_Ah + (size_t)(m0 + (tid >> 3)) * 4096 + (tid & 7) * 16;
    const char* pB = (const char*)g_Bh + (size_t)(n0 + (tid >> 3)) * 4096 + (tid & 7) * 16;

    float acc[4][4][4];
    #pragma unroll
    for (int i = 0; i < 4; i++)
        #pragma unroll
        for (int j = 0; j < 4; j++)
            #pragma unroll
            for (int t = 0; t < 4; t++) acc[i][j][t] = 0.0f;

    // per-lane swizzled ldsm bases
    const int a_row_l = lane & 15;
    const uint32_t a_kb = (uint32_t)((lane >> 4) << 4);
    const int b_j = lane >> 3;
    const int b_row_l = (lane & 7) + ((b_j >> 1) << 3);
    const uint32_t b_kb = (uint32_t)((b_j & 1) << 4);

    uint32_t baseA[4], xA[4];
    #pragma unroll
    for (int mt = 0; mt < 4; mt++) {
        int row = warp_m * 64 + mt * 16 + a_row_l;
        baseA[mt] = (uint32_t)(row << 7);
        xA[mt]    = (uint32_t)((row & 7) << 4);
    }
    uint32_t baseB[2], xB[2];
    #pragma unroll
    for (int np = 0; np < 2; np++) {
        int row = warp_n * 32 + np * 16 + b_row_l;
        baseB[np] = (uint32_t)(row << 7);
        xB[np]    = (uint32_t)((row & 7) << 4);
    }

    // one chunk of compute from a compile-time stage base
    auto compute_chunk = [&](uint32_t stage) {
        #pragma unroll
        for (int ks = 0; ks < 4; ks++) {
            const uint32_t kb = (uint32_t)(ks * 32);
            uint32_t bh[4][2];
            #pragma unroll
            for (int np = 0; np < 2; np++) {
                uint32_t ad = stage + SB + baseB[np] + ((kb + b_kb) ^ xB[np]);
                uint32_t r0, r1, r2, r3;
                ldsm4(ad, r0, r1, r2, r3);
                bh[np * 2 + 0][0] = r0; bh[np * 2 + 0][1] = r1;
                bh[np * 2 + 1][0] = r2; bh[np * 2 + 1][1] = r3;
            }
            uint32_t ah[2][4];
            {
                uint32_t ad = stage + SA + baseA[0] + ((kb + a_kb) ^ xA[0]);
                ldsm4(ad, ah[0][0], ah[0][1], ah[0][2], ah[0][3]);
            }
            #pragma unroll
            for (int mt = 0; mt < 4; mt++) {
                const int cb = mt & 1;
                if (mt < 3) {
                    const int nb = (mt + 1) & 1;
                    uint32_t ad = stage + SA + baseA[mt + 1] + ((kb + a_kb) ^ xA[mt + 1]);
                    ldsm4(ad, ah[nb][0], ah[nb][1], ah[nb][2], ah[nb][3]);
                }
                #pragma unroll
                for (int nt = 0; nt < 4; nt++)
                    mma16816(acc[mt][nt][0], acc[mt][nt][1], acc[mt][nt][2], acc[mt][nt][3],
                             ah[cb][0], ah[cb][1], ah[cb][2], ah[cb][3],
                             bh[nt][0], bh[nt][1]);
            }
        }
    };

    const uint32_t st0 = sb, st1 = sb + STAGE_BYTES, st2 = sb + 2 * STAGE_BYTES;

    // prologue: fill 3 stages (chunks 0,1,2)
    fill_stage2(st0, s0, pA, pB, 0); cp_commit();
    fill_stage2(st1, s0, pA, pB, 1); cp_commit();
    fill_stage2(st2, s0, pA, pB, 2); cp_commit();

    // one pipeline iteration: wait, sync, refill prev slot with chunk k+2, compute
    auto iter = [&](int k, uint32_t stage, uint32_t prevslot, bool dofill) {
        cp_wait1();
        __syncthreads();
        if (dofill) {
            int kc = k + 2;
            if (kc < NCHUNK) fill_stage2(prevslot, s0, pA, pB, kc);
            cp_commit();
        }
        compute_chunk(stage);
    };

    iter(0, st0, st2, false);
    iter(1, st1, st0, true);
    iter(2, st2, st1, true);
    #pragma unroll 1
    for (int ko = 3; ko < 30; ko += 3) {
        iter(ko,     st0, st2, true);
        iter(ko + 1, st1, st0, true);
        iter(ko + 2, st2, st1, true);
    }
    iter(30, st0, st2, true);   // kc=32 -> commit-only
    iter(31, st1, st0, true);   // kc=33 -> commit-only

    // ---------------- epilogue: fused elu, float2 stores ----------------
    const int gp  = lane >> 2;
    const int tg2 = (lane & 3) * 2;
    #pragma unroll
    for (int mt = 0; mt < 4; mt++) {
        int mrow = m0 + warp_m * 64 + mt * 16 + gp;
        #pragma unroll
        for (int nt = 0; nt < 4; nt++) {
            int ncol = n0 + warp_n * 32 + nt * 8 + tg2;
            float2 v0, v1;
            v0.x = elu_f(acc[mt][nt][0]);
            v0.y = elu_f(acc[mt][nt][1]);
            v1.x = elu_f(acc[mt][nt][2]);
            v1.y = elu_f(acc[mt][nt][3]);
            *reinterpret_cast<float2*>(C + (size_t)mrow * GN + ncol) = v0;
            *reinterpret_cast<float2*>(C + (size_t)(mrow + 8) * GN + ncol) = v1;
        }
    }
}

// ---------------- launch ----------------
extern "C" void kernel_launch(void* const* d_in, const int* in_sizes, int n_in,
                              void* d_out, int out_size) {
    const float* input = (const float*)d_in[0];   // [8192, 2048]
    const float* W     = (const float*)d_in[2];   // [2048, 2048]
    float*       out   = (float*)d_out;

    cudaFuncSetAttribute(gat_mma_kernel,
                         cudaFuncAttributeMaxDynamicSharedMemorySize, SMEM_TOTAL);

    conv_kernel<<<CONV_A_BLOCKS + 4096, 256>>>(input, W);
    gat_mma_kernel<<<dim3(GN / BN, GM / BM), NTHREADS, SMEM_TOTAL>>>(out);
}

// round 16
// speedup vs baseline: 1.2233x; 1.0175x over previous
#include <cuda_runtime.h>
#include <cuda_fp16.h>
#include <cstdint>

// out = elu(input @ W)  [reference's softmax(eye-mask) == Identity exactly]
// fp32 GEMM M=8192 N=2048 K=2048, single fp16 term on mma.sync.m16n8k16
// (measured rel_err 3.0e-4 < 1e-3).
// R15: R14 platform (occ-2, CTA 128x128, 8 warps, warp 64x32, 3-stage static
//   unroll — best at 178.9us / mainloop 159.7 / tensor 72.2%). Changes:
//   - refill cp.asyncs moved AFTER ks=0 compute: MMA issue starts immediately
//     at each chunk boundary instead of behind 12 fill-issue ops (refill
//     targets prevslot != stage, so ks=0 reads are unaffected; one commit per
//     iter keeps wait_group accounting identical).
//   - conv A: 4 back-to-back float4 loads per thread (MLP 2->4).

#define GM 8192
#define GN 2048
#define GK 2048

#define BM 128
#define BN 128
#define BK 64
#define NTHREADS 256
#define NCHUNK (GK / BK)   // 32

// ---------------- scratch (fp16 operands) ----------------
__device__ __half g_Ah[(size_t)GM * GK];
__device__ __half g_Bh[(size_t)GN * GK];   // W^T, K-major rows

// ---------------- smem stage layout ----------------
#define SA 0
#define SB 16384
#define STAGE_BYTES 32768
#define NSTAGE 3
#define SMEM_TOTAL (NSTAGE * STAGE_BYTES)   // 98304/CTA; x2 CTAs = 192KB/SM

__device__ __forceinline__ uint32_t smem_u32(const void* p) {
    uint32_t a;
    asm("{ .reg .u64 t; cvta.to.shared.u64 t, %1; cvt.u32.u64 %0, t; }" : "=r"(a) : "l"(p));
    return a;
}
__device__ __forceinline__ void cp16(uint32_t dst, const void* src) {
    asm volatile("cp.async.cg.shared.global [%0], [%1], 16;" :: "r"(dst), "l"(src));
}
__device__ __forceinline__ void cp_commit() {
    asm volatile("cp.async.commit_group;" ::: "memory");
}
__device__ __forceinline__ void cp_wait1() {
    asm volatile("cp.async.wait_group 1;" ::: "memory");
}
__device__ __forceinline__ void ldsm4(uint32_t addr, uint32_t& r0, uint32_t& r1,
                                      uint32_t& r2, uint32_t& r3) {
    asm volatile("ldmatrix.sync.aligned.m8n8.x4.shared.b16 {%0,%1,%2,%3}, [%4];"
                 : "=r"(r0), "=r"(r1), "=r"(r2), "=r"(r3) : "r"(addr));
}
__device__ __forceinline__ void mma16816(float& d0, float& d1, float& d2, float& d3,
                                         uint32_t a0, uint32_t a1, uint32_t a2, uint32_t a3,
                                         uint32_t b0, uint32_t b1) {
    asm volatile(
        "mma.sync.aligned.m16n8k16.row.col.f32.f16.f16.f32 "
        "{%0,%1,%2,%3}, {%4,%5,%6,%7}, {%8,%9}, {%0,%1,%2,%3};"
        : "+f"(d0), "+f"(d1), "+f"(d2), "+f"(d3)
        : "r"(a0), "r"(a1), "r"(a2), "r"(a3), "r"(b0), "r"(b1));
}
__device__ __forceinline__ float elu_f(float x) { return x > 0.0f ? x : expm1f(x); }

// ---------------- merged conversion kernel ----------------
// blocks [0, 4096): A fp32 -> fp16, 16 floats/thread, 4 wide loads up front
// blocks [4096, 8192): W fp32 -> W^T fp16, smem transpose, half2 stores
#define CONV_A_BLOCKS 4096
__global__ __launch_bounds__(256) void conv_kernel(const float* __restrict__ A,
                                                   const float* __restrict__ B) {
    __shared__ float tile[32][33];
    int bid = blockIdx.x;
    int tid = threadIdx.x;
    if (bid < CONV_A_BLOCKS) {
        const float4* A4 = reinterpret_cast<const float4*>(A);
        size_t u = (size_t)bid * 512 + tid;    // base output float4 index
        float4 v[4];
        #pragma unroll
        for (int i = 0; i < 4; i++) v[i] = A4[(u + (size_t)(i >> 1) * 256) * 2 + (i & 1)];
        #pragma unroll
        for (int i = 0; i < 2; i++) {
            __half2 h0 = __half2(__float2half(v[i*2].x),   __float2half(v[i*2].y));
            __half2 h1 = __half2(__float2half(v[i*2].z),   __float2half(v[i*2].w));
            __half2 h2 = __half2(__float2half(v[i*2+1].x), __float2half(v[i*2+1].y));
            __half2 h3 = __half2(__float2half(v[i*2+1].z), __float2half(v[i*2+1].w));
            float4 out;
            out.x = __uint_as_float(*reinterpret_cast<uint32_t*>(&h0));
            out.y = __uint_as_float(*reinterpret_cast<uint32_t*>(&h1));
            out.z = __uint_as_float(*reinterpret_cast<uint32_t*>(&h2));
            out.w = __uint_as_float(*reinterpret_cast<uint32_t*>(&h3));
            reinterpret_cast<float4*>(g_Ah)[u + (size_t)i * 256] = out;
        }
    } else {
        int b = bid - CONV_A_BLOCKS;          // 0..4095
        int n0 = (b & 63) * 32;
        int k0 = (b >> 6) * 32;
        int tx = tid & 31, ty = tid >> 5;     // read phase (32,8)
        #pragma unroll
        for (int j = 0; j < 32; j += 8)
            tile[ty + j][tx] = B[(size_t)(k0 + ty + j) * GN + n0 + tx];
        __syncthreads();
        int kp = tid & 15, nl = tid >> 4;     // write phase: half2 along K
        #pragma unroll
        for (int j = 0; j < 32; j += 16) {
            int n = nl + j;
            __half2 h = __half2(__float2half(tile[kp * 2][n]),
                                __float2half(tile[kp * 2 + 1][n]));
            *reinterpret_cast<__half2*>(g_Bh + (size_t)(n0 + n) * GK + k0 + kp * 2) = h;
        }
    }
}

// ---------------- hoisted stage fill (one BK=64 chunk) ----------------
__device__ __forceinline__ void fill_stage2(uint32_t sbase, uint32_t s0,
                                            const char* pA, const char* pB,
                                            int kc) {
    const size_t koff = (size_t)kc * 128;
    #pragma unroll
    for (int j = 0; j < 4; j++) {
        cp16(sbase + SA + s0 + j * 4096, pA + koff + (size_t)j * 131072);
        cp16(sbase + SB + s0 + j * 4096, pB + koff + (size_t)j * 131072);
    }
}

// ---------------- main GEMM kernel ----------------
__global__ __launch_bounds__(NTHREADS, 2)
void gat_mma_kernel(float* __restrict__ C) {
    extern __shared__ char smem[];
    uint32_t sb = smem_u32(smem);
    const int tid  = threadIdx.x;
    const int wid  = tid >> 5;
    const int lane = tid & 31;
    const int m0 = blockIdx.y * BM;
    const int n0 = blockIdx.x * BN;
    const int warp_m = wid & 1;    // 2 M-tiles of 64
    const int warp_n = wid >> 1;   // 4 N-tiles of 32

    // per-thread fill addressing (hoisted; SW128 mask invariant across strides)
    const uint32_t s0 = (uint32_t)((tid >> 3) * 128 +
                        (((tid & 7) * 16) ^ (((tid >> 3) & 7) << 4)));
    const char* pA = (const char*)g_Ah + (size_t)(m0 + (tid >> 3)) * 4096 + (tid & 7) * 16;
    const char* pB = (const char*)g_Bh + (size_t)(n0 + (tid >> 3)) * 4096 + (tid & 7) * 16;

    float acc[4][4][4];
    #pragma unroll
    for (int i = 0; i < 4; i++)
        #pragma unroll
        for (int j = 0; j < 4; j++)
            #pragma unroll
            for (int t = 0; t < 4; t++) acc[i][j][t] = 0.0f;

    // per-lane swizzled ldsm bases
    const int a_row_l = lane & 15;
    const uint32_t a_kb = (uint32_t)((lane >> 4) << 4);
    const int b_j = lane >> 3;
    const int b_row_l = (lane & 7) + ((b_j >> 1) << 3);
    const uint32_t b_kb = (uint32_t)((b_j & 1) << 4);

    uint32_t baseA[4], xA[4];
    #pragma unroll
    for (int mt = 0; mt < 4; mt++) {
        int row = warp_m * 64 + mt * 16 + a_row_l;
        baseA[mt] = (uint32_t)(row << 7);
        xA[mt]    = (uint32_t)((row & 7) << 4);
    }
    uint32_t baseB[2], xB[2];
    #pragma unroll
    for (int np = 0; np < 2; np++) {
        int row = warp_n * 32 + np * 16 + b_row_l;
        baseB[np] = (uint32_t)(row << 7);
        xB[np]    = (uint32_t)((row & 7) << 4);
    }

    // one ks-slice of compute (4 ldsm + 16 MMA for ks; A double-buffered)
    auto compute_ks = [&](uint32_t stage, int ks) {
        const uint32_t kb = (uint32_t)(ks * 32);
        uint32_t bh[4][2];
        #pragma unroll
        for (int np = 0; np < 2; np++) {
            uint32_t ad = stage + SB + baseB[np] + ((kb + b_kb) ^ xB[np]);
            uint32_t r0, r1, r2, r3;
            ldsm4(ad, r0, r1, r2, r3);
            bh[np * 2 + 0][0] = r0; bh[np * 2 + 0][1] = r1;
            bh[np * 2 + 1][0] = r2; bh[np * 2 + 1][1] = r3;
        }
        uint32_t ah[2][4];
        {
            uint32_t ad = stage + SA + baseA[0] + ((kb + a_kb) ^ xA[0]);
            ldsm4(ad, ah[0][0], ah[0][1], ah[0][2], ah[0][3]);
        }
        #pragma unroll
        for (int mt = 0; mt < 4; mt++) {
            const int cb = mt & 1;
            if (mt < 3) {
                const int nb = (mt + 1) & 1;
                uint32_t ad = stage + SA + baseA[mt + 1] + ((kb + a_kb) ^ xA[mt + 1]);
                ldsm4(ad, ah[nb][0], ah[nb][1], ah[nb][2], ah[nb][3]);
            }
            #pragma unroll
            for (int nt = 0; nt < 4; nt++)
                mma16816(acc[mt][nt][0], acc[mt][nt][1], acc[mt][nt][2], acc[mt][nt][3],
                         ah[cb][0], ah[cb][1], ah[cb][2], ah[cb][3],
                         bh[nt][0], bh[nt][1]);
        }
    };

    const uint32_t st0 = sb, st1 = sb + STAGE_BYTES, st2 = sb + 2 * STAGE_BYTES;

    // prologue: fill 3 stages (chunks 0,1,2)
    fill_stage2(st0, s0, pA, pB, 0); cp_commit();
    fill_stage2(st1, s0, pA, pB, 1); cp_commit();
    fill_stage2(st2, s0, pA, pB, 2); cp_commit();

    // pipeline iteration: wait, sync, compute ks0, THEN refill prev slot
    // (prevslot != stage so ks0 reads are unaffected), compute ks1..3.
    auto iter = [&](int k, uint32_t stage, uint32_t prevslot, bool dofill) {
        cp_wait1();
        __syncthreads();
        compute_ks(stage, 0);
        if (dofill) {
            int kc = k + 2;
            if (kc < NCHUNK) fill_stage2(prevslot, s0, pA, pB, kc);
            cp_commit();
        }
        compute_ks(stage, 1);
        compute_ks(stage, 2);
        compute_ks(stage, 3);
    };

    iter(0, st0, st2, false);
    iter(1, st1, st0, true);
    iter(2, st2, st1, true);
    #pragma unroll 1
    for (int ko = 3; ko < 30; ko += 3) {
        iter(ko,     st0, st2, true);
        iter(ko + 1, st1, st0, true);
        iter(ko + 2, st2, st1, true);
    }
    iter(30, st0, st2, true);   // kc=32 -> commit-only
    iter(31, st1, st0, true);   // kc=33 -> commit-only

    // ---------------- epilogue: fused elu, float2 stores ----------------
    const int gp  = lane >> 2;
    const int tg2 = (lane & 3) * 2;
    #pragma unroll
    for (int mt = 0; mt < 4; mt++) {
        int mrow = m0 + warp_m * 64 + mt * 16 + gp;
        #pragma unroll
        for (int nt = 0; nt < 4; nt++) {
            int ncol = n0 + warp_n * 32 + nt * 8 + tg2;
            float2 v0, v1;
            v0.x = elu_f(acc[mt][nt][0]);
            v0.y = elu_f(acc[mt][nt][1]);
            v1.x = elu_f(acc[mt][nt][2]);
            v1.y = elu_f(acc[mt][nt][3]);
            *reinterpret_cast<float2*>(C + (size_t)mrow * GN + ncol) = v0;
            *reinterpret_cast<float2*>(C + (size_t)(mrow + 8) * GN + ncol) = v1;
        }
    }
}

// ---------------- launch ----------------
extern "C" void kernel_launch(void* const* d_in, const int* in_sizes, int n_in,
                              void* d_out, int out_size) {
    const float* input = (const float*)d_in[0];   // [8192, 2048]
    const float* W     = (const float*)d_in[2];   // [2048, 2048]
    float*       out   = (float*)d_out;

    cudaFuncSetAttribute(gat_mma_kernel,
                         cudaFuncAttributeMaxDynamicSharedMemorySize, SMEM_TOTAL);

    conv_kernel<<<CONV_A_BLOCKS + 4096, 256>>>(input, W);
    gat_mma_kernel<<<dim3(GN / BN, GM / BM), NTHREADS, SMEM_TOTAL>>>(out);
}